// round 9
// baseline (speedup 1.0000x reference)
#include <cuda_runtime.h>
#include <cuda_bf16.h>
#include <cuda_fp16.h>
#include <math.h>
#include <stdint.h>

#define TOKENS 16384
#define DDIM   2048
#define NEXP   64
#define HDIM   1024

// Output layout (float32): idx [16384*2] | scores [16384*2] | probs [16384*64] | imp [64] | load [64]
#define OFF_IDX   0
#define OFF_SC    32768
#define OFF_P     65536
#define OFF_IMP   1114112
#define OFF_LOAD  1114176

// ---------------- scratch ----------------
__device__ __half g_w1[(size_t)HDIM * DDIM];
__device__ __nv_bfloat16 g_wg_hi[(size_t)NEXP * DDIM];
__device__ __nv_bfloat16 g_wg_lo[(size_t)NEXP * DDIM];
__device__ float g_logits[(size_t)TOKENS * NEXP];
__device__ float g_diffpre[TOKENS];
__device__ float g_mu[TOKENS];
__device__ float g_rstd[TOKENS];
__device__ float g_imp[NEXP];
__device__ int   g_loadcnt[NEXP];

// ---------------- prep ----------------
__global__ void prep_kernel(const float* __restrict__ W1, const float* __restrict__ Wg) {
    int i = blockIdx.x * blockDim.x + threadIdx.x;
    g_w1[i] = __float2half(W1[i]);
    if (i < NEXP * DDIM) {
        float v = Wg[i];
        __nv_bfloat16 hi = __float2bfloat16(v);
        g_wg_hi[i] = hi;
        g_wg_lo[i] = __float2bfloat16(v - __bfloat162float(hi));
    }
    if (i < TOKENS) g_diffpre[i] = 0.f;
    if (i < NEXP) { g_loadcnt[i] = 0; g_imp[i] = 0.f; }
}

// =========================================================================
// ln_logits: LN stats + base-logits GEMM (bf16x3 split), pass-1 only.
// One CTA = 128 tokens, 512 threads (16 warps, warp tile 16 x 32).
// =========================================================================
#define AST 40

__global__ __launch_bounds__(512)
void ln_logits(const float* __restrict__ x) {
    __shared__ __align__(16) __nv_bfloat16 Ah[128 * AST];
    __shared__ __align__(16) __nv_bfloat16 Al[128 * AST];
    __shared__ __align__(16) __nv_bfloat16 Wh[64 * AST];
    __shared__ __align__(16) __nv_bfloat16 Wl[64 * AST];
    __shared__ float sS[128 * 4], sQ[128 * 4];

    int tile = blockIdx.x;
    int tid = threadIdx.x;
    int warp = tid >> 5, lane = tid & 31;
    const float* xb = x + (size_t)tile * 128 * DDIM;

    int lr = tid >> 2;
    int lc = (tid & 3) * 8;
    int wm = (warp & 7) * 16;
    int wn2 = (warp >> 3) * 32;

    float s = 0.f, q = 0.f;
    float acc[4][4];
    #pragma unroll
    for (int j = 0; j < 4; j++)
        #pragma unroll
        for (int r = 0; r < 4; r++) acc[j][r] = 0.f;

    float4 v0 = *(const float4*)&xb[(size_t)lr * DDIM + lc];
    float4 v1 = *(const float4*)&xb[(size_t)lr * DDIM + lc + 4];
    uint4 wh, wl;
    if (tid < 256) {
        wh = *(const uint4*)&g_wg_hi[(size_t)(tid >> 2) * DDIM + (tid & 3) * 8];
        wl = *(const uint4*)&g_wg_lo[(size_t)(tid >> 2) * DDIM + (tid & 3) * 8];
    }

    for (int kc = 0; kc < 64; kc++) {
        if (tid < 256) {
            *(uint4*)&Wh[(tid >> 2) * AST + (tid & 3) * 8] = wh;
            *(uint4*)&Wl[(tid >> 2) * AST + (tid & 3) * 8] = wl;
        }
        {
            s += v0.x + v0.y + v0.z + v0.w + v1.x + v1.y + v1.z + v1.w;
            q += v0.x*v0.x + v0.y*v0.y + v0.z*v0.z + v0.w*v0.w
               + v1.x*v1.x + v1.y*v1.y + v1.z*v1.z + v1.w*v1.w;
            __align__(16) __nv_bfloat16 hb[8], lb[8];
            float vv[8] = {v0.x, v0.y, v0.z, v0.w, v1.x, v1.y, v1.z, v1.w};
            #pragma unroll
            for (int i = 0; i < 8; i++) {
                __nv_bfloat16 b = __float2bfloat16(vv[i]);
                hb[i] = b;
                lb[i] = __float2bfloat16(vv[i] - __bfloat162float(b));
            }
            *(uint4*)&Ah[lr * AST + lc] = *(uint4*)hb;
            *(uint4*)&Al[lr * AST + lc] = *(uint4*)lb;
        }
        __syncthreads();

        if (kc < 63) {
            int k0n = (kc + 1) * 32;
            v0 = *(const float4*)&xb[(size_t)lr * DDIM + k0n + lc];
            v1 = *(const float4*)&xb[(size_t)lr * DDIM + k0n + lc + 4];
            if (tid < 256) {
                wh = *(const uint4*)&g_wg_hi[(size_t)(tid >> 2) * DDIM + k0n + (tid & 3) * 8];
                wl = *(const uint4*)&g_wg_lo[(size_t)(tid >> 2) * DDIM + k0n + (tid & 3) * 8];
            }
        }

        #pragma unroll
        for (int ks = 0; ks < 2; ks++) {
            int arow = wm + (lane >> 2);
            int colb = (lane & 3) * 2 + ks * 16;
            const __nv_bfloat16* pa  = &Ah[arow * AST + colb];
            const __nv_bfloat16* pal = &Al[arow * AST + colb];
            uint32_t ah[4], al[4];
            ah[0] = *(const uint32_t*)(pa);
            ah[1] = *(const uint32_t*)(pa + 8 * AST);
            ah[2] = *(const uint32_t*)(pa + 8);
            ah[3] = *(const uint32_t*)(pa + 8 * AST + 8);
            al[0] = *(const uint32_t*)(pal);
            al[1] = *(const uint32_t*)(pal + 8 * AST);
            al[2] = *(const uint32_t*)(pal + 8);
            al[3] = *(const uint32_t*)(pal + 8 * AST + 8);
            #pragma unroll
            for (int j = 0; j < 4; j++) {
                int brow = wn2 + j * 8 + (lane >> 2);
                const __nv_bfloat16* pb  = &Wh[brow * AST + colb];
                const __nv_bfloat16* pbl = &Wl[brow * AST + colb];
                uint32_t bh0 = *(const uint32_t*)(pb);
                uint32_t bh1 = *(const uint32_t*)(pb + 8);
                uint32_t bl0 = *(const uint32_t*)(pbl);
                uint32_t bl1 = *(const uint32_t*)(pbl + 8);
                asm volatile(
                    "mma.sync.aligned.m16n8k16.row.col.f32.bf16.bf16.f32 "
                    "{%0,%1,%2,%3}, {%4,%5,%6,%7}, {%8,%9}, {%0,%1,%2,%3};\n"
                    : "+f"(acc[j][0]), "+f"(acc[j][1]), "+f"(acc[j][2]), "+f"(acc[j][3])
                    : "r"(ah[0]), "r"(ah[1]), "r"(ah[2]), "r"(ah[3]), "r"(bh0), "r"(bh1));
                asm volatile(
                    "mma.sync.aligned.m16n8k16.row.col.f32.bf16.bf16.f32 "
                    "{%0,%1,%2,%3}, {%4,%5,%6,%7}, {%8,%9}, {%0,%1,%2,%3};\n"
                    : "+f"(acc[j][0]), "+f"(acc[j][1]), "+f"(acc[j][2]), "+f"(acc[j][3])
                    : "r"(ah[0]), "r"(ah[1]), "r"(ah[2]), "r"(ah[3]), "r"(bl0), "r"(bl1));
                asm volatile(
                    "mma.sync.aligned.m16n8k16.row.col.f32.bf16.bf16.f32 "
                    "{%0,%1,%2,%3}, {%4,%5,%6,%7}, {%8,%9}, {%0,%1,%2,%3};\n"
                    : "+f"(acc[j][0]), "+f"(acc[j][1]), "+f"(acc[j][2]), "+f"(acc[j][3])
                    : "r"(al[0]), "r"(al[1]), "r"(al[2]), "r"(al[3]), "r"(bh0), "r"(bh1));
            }
        }
        __syncthreads();
    }

    sS[lr * 4 + (tid & 3)] = s;
    sQ[lr * 4 + (tid & 3)] = q;
    __syncthreads();
    if (tid < 128) {
        float ts = sS[tid*4] + sS[tid*4+1] + sS[tid*4+2] + sS[tid*4+3];
        float tq = sQ[tid*4] + sQ[tid*4+1] + sQ[tid*4+2] + sQ[tid*4+3];
        float mean = ts * (1.f / DDIM);
        float var  = tq * (1.f / DDIM) - mean * mean;
        g_mu[tile * 128 + tid]   = mean;
        g_rstd[tile * 128 + tid] = rsqrtf(var + 1e-5f);
    }

    #pragma unroll
    for (int j = 0; j < 4; j++) {
        int row = tile * 128 + wm + (lane >> 2);
        int col = wn2 + j * 8 + (lane & 3) * 2;
        float2 c01; c01.x = acc[j][0]; c01.y = acc[j][1];
        float2 c23; c23.x = acc[j][2]; c23.y = acc[j][3];
        *(float2*)&g_logits[(size_t)row * NEXP + col] = c01;
        *(float2*)&g_logits[(size_t)(row + 8) * NEXP + col] = c23;
    }
}

// =========================================================================
// gemm1: BM=128 x BN=256 x BK=32, fp16 MMA with fp16 chunk-accum -> fp32.
// LN applied in-kernel from x fp32. 3-stage cp.async B-ring.
// =========================================================================
#define G2_STAGES 3
#define G2_BK     32
#define G2_BN     256
#define G2_BBYTES 16384
#define G2_ABYTES 8192
#define G2_A_OFF  (G2_STAGES * G2_BBYTES)
#define G2_GB_OFF (G2_A_OFF + 2 * G2_ABYTES)
#define G2_SMEM   (G2_GB_OFF + 16384)
#define G2_CHUNKS (DDIM / G2_BK)

__device__ __forceinline__ uint32_t smem_u32(const void* p) {
    uint32_t a;
    asm("{ .reg .u64 t; cvta.to.shared.u64 t, %1; cvt.u32.u64 %0, t; }" : "=r"(a) : "l"(p));
    return a;
}
__device__ __forceinline__ uint32_t g1_sw(uint32_t r, uint32_t c) {
    return r * 64 + ((c ^ ((r >> 1) & 3)) * 16);
}
__device__ __forceinline__ void ldsm_x4(uint32_t& r0, uint32_t& r1, uint32_t& r2, uint32_t& r3,
                                        uint32_t addr) {
    asm volatile("ldmatrix.sync.aligned.m8n8.x4.shared.b16 {%0,%1,%2,%3}, [%4];"
                 : "=r"(r0), "=r"(r1), "=r"(r2), "=r"(r3) : "r"(addr));
}
__device__ __forceinline__ float gelu_exact(float v) {
    return 0.5f * v * (1.0f + erff(v * 0.70710678118654752440f));
}
// fp16 in, fp16 accum MMA
#define MMA_F16(d0, d1, a, b0, b1) \
    asm volatile( \
        "mma.sync.aligned.m16n8k16.row.col.f16.f16.f16.f16 " \
        "{%0,%1}, {%2,%3,%4,%5}, {%6,%7}, {%0,%1};\n" \
        : "+r"(d0), "+r"(d1) \
        : "r"((a)[0]), "r"((a)[1]), "r"((a)[2]), "r"((a)[3]), "r"(b0), "r"(b1))

__device__ __forceinline__ void g2_stage_B(uint32_t sB, const __half* Bg,
                                           int k0, int tid) {
    #pragma unroll
    for (int i = 0; i < 4; i++) {
        int idx = tid + i * 256;
        int r = idx >> 2, c = idx & 3;
        uint32_t dst = sB + g1_sw(r, c);
        asm volatile("cp.async.cg.shared.global [%0], [%1], 16;\n"
                     :: "r"(dst), "l"(Bg + (size_t)r * DDIM + k0 + c * 8));
    }
    asm volatile("cp.async.commit_group;\n");
}

__global__ __launch_bounds__(256, 1)
void gemm1_mma(const float* __restrict__ x, const float* __restrict__ gamma,
               const float* __restrict__ beta, const float* __restrict__ W2) {
    extern __shared__ __align__(128) char g1sm[];
    uint32_t sb = smem_u32(g1sm);
    int tid = threadIdx.x;
    int warp = tid >> 5, lane = tid & 31;
    int bn = blockIdx.x, bm = blockIdx.y;
    int wm = (warp & 1) * 64;
    int wn = (warp >> 1) * 64;

    const float* xb = x + (size_t)(bm * 128) * DDIM;
    const __half* Bg = g_w1 + (size_t)(bn * G2_BN) * DDIM;

    float* sGB = (float*)(g1sm + G2_GB_OFF);
    #pragma unroll
    for (int i = 0; i < 2; i++) {
        int idx = tid + i * 256;
        ((float4*)sGB)[idx]       = ((const float4*)gamma)[idx];
        ((float4*)sGB)[idx + 512] = ((const float4*)beta)[idx];
    }

    int r0 = tid >> 1;
    int hsel = tid & 1;
    float mu = g_mu[bm * 128 + r0];
    float rs = g_rstd[bm * 128 + r0];

    float acc[4][8][4];
    #pragma unroll
    for (int i = 0; i < 4; i++)
        #pragma unroll
        for (int j = 0; j < 8; j++)
            #pragma unroll
            for (int r = 0; r < 4; r++) acc[i][j][r] = 0.f;

    g2_stage_B(sb + 0 * G2_BBYTES, Bg, 0, tid);
    g2_stage_B(sb + 1 * G2_BBYTES, Bg, G2_BK, tid);
    float4 xv[4];
    #pragma unroll
    for (int i = 0; i < 4; i++)
        xv[i] = *(const float4*)&xb[(size_t)r0 * DDIM + hsel * 16 + i * 4];

    __syncthreads();

    int lrow = lane & 15;
    int lsel = lane >> 4;

    #pragma unroll 1
    for (int c = 0; c < G2_CHUNKS; c++) {
        if (c + 2 < G2_CHUNKS)
            g2_stage_B(sb + ((c + 2) % G2_STAGES) * G2_BBYTES, Bg, (c + 2) * G2_BK, tid);

        {
            const float* gg = sGB + c * 32 + hsel * 16;
            const float* bb = gg + 2048;
            uint32_t sA = sb + G2_A_OFF + (c & 1) * G2_ABYTES;
            __align__(16) __half ob[16];
            #pragma unroll
            for (int i = 0; i < 4; i++) {
                float4 t4 = xv[i];
                float4 g4 = *(const float4*)(gg + i * 4);
                float4 b4 = *(const float4*)(bb + i * 4);
                ob[i*4+0] = __float2half((t4.x - mu) * rs * g4.x + b4.x);
                ob[i*4+1] = __float2half((t4.y - mu) * rs * g4.y + b4.y);
                ob[i*4+2] = __float2half((t4.z - mu) * rs * g4.z + b4.z);
                ob[i*4+3] = __float2half((t4.w - mu) * rs * g4.w + b4.w);
            }
            #pragma unroll
            for (int j = 0; j < 2; j++) {
                uint32_t dst = sA + g1_sw((uint32_t)r0, (uint32_t)(hsel * 2 + j));
                *(uint4*)(g1sm + (dst - sb)) = *(uint4*)&ob[j * 8];
            }
        }

        if (c + 1 < G2_CHUNKS) {
            #pragma unroll
            for (int i = 0; i < 4; i++)
                xv[i] = *(const float4*)&xb[(size_t)r0 * DDIM + (c + 1) * G2_BK + hsel * 16 + i * 4];
        }

        if (c + 2 < G2_CHUNKS) {
            asm volatile("cp.async.wait_group 2;\n");
        } else if (c + 2 == G2_CHUNKS) {
            asm volatile("cp.async.wait_group 1;\n");
        } else {
            asm volatile("cp.async.wait_group 0;\n");
        }
        __syncthreads();

        uint32_t sA = sb + G2_A_OFF + (c & 1) * G2_ABYTES;
        uint32_t sB = sb + (c % G2_STAGES) * G2_BBYTES;

        // fp16 chunk accumulators (zeroed each chunk)
        uint32_t hc[4][8][2];
        #pragma unroll
        for (int i = 0; i < 4; i++)
            #pragma unroll
            for (int j = 0; j < 8; j++) { hc[i][j][0] = 0u; hc[i][j][1] = 0u; }

        #pragma unroll
        for (int ks = 0; ks < 2; ks++) {
            uint32_t af[4][4], bf[8][2];
            #pragma unroll
            for (int i = 0; i < 4; i++) {
                uint32_t r = (uint32_t)(wm + i * 16 + lrow);
                ldsm_x4(af[i][0], af[i][1], af[i][2], af[i][3],
                        sA + g1_sw(r, (uint32_t)(ks * 2 + lsel)));
            }
            #pragma unroll
            for (int jb = 0; jb < 4; jb++) {
                uint32_t r = (uint32_t)(wn + jb * 16 + lrow);
                uint32_t q0, q1, q2, q3;
                ldsm_x4(q0, q1, q2, q3, sB + g1_sw(r, (uint32_t)(ks * 2 + lsel)));
                bf[jb * 2][0] = q0;     bf[jb * 2][1] = q2;
                bf[jb * 2 + 1][0] = q1; bf[jb * 2 + 1][1] = q3;
            }
            #pragma unroll
            for (int i = 0; i < 4; i++)
                #pragma unroll
                for (int j = 0; j < 8; j++)
                    MMA_F16(hc[i][j][0], hc[i][j][1], af[i], bf[j][0], bf[j][1]);
        }

        // flush fp16 chunk sums into fp32 accumulators
        #pragma unroll
        for (int i = 0; i < 4; i++)
            #pragma unroll
            for (int j = 0; j < 8; j++) {
                float2 lo = __half22float2(*(__half2*)&hc[i][j][0]);
                float2 hi = __half22float2(*(__half2*)&hc[i][j][1]);
                acc[i][j][0] += lo.x; acc[i][j][1] += lo.y;
                acc[i][j][2] += hi.x; acc[i][j][3] += hi.y;
            }
        __syncthreads();
    }

    float part0[4] = {0.f, 0.f, 0.f, 0.f};
    float part1[4] = {0.f, 0.f, 0.f, 0.f};
    #pragma unroll
    for (int j = 0; j < 8; j++) {
        int n = bn * G2_BN + wn + j * 8 + (lane & 3) * 2;
        float w20 = W2[n], w21 = W2[n + 1];
        #pragma unroll
        for (int i = 0; i < 4; i++) {
            part0[i] += gelu_exact(acc[i][j][0]) * w20 + gelu_exact(acc[i][j][1]) * w21;
            part1[i] += gelu_exact(acc[i][j][2]) * w20 + gelu_exact(acc[i][j][3]) * w21;
        }
    }
    #pragma unroll
    for (int i = 0; i < 4; i++) {
        part0[i] += __shfl_xor_sync(0xffffffffu, part0[i], 1);
        part0[i] += __shfl_xor_sync(0xffffffffu, part0[i], 2);
        part1[i] += __shfl_xor_sync(0xffffffffu, part1[i], 1);
        part1[i] += __shfl_xor_sync(0xffffffffu, part1[i], 2);
    }
    if ((lane & 3) == 0) {
        int mbase = bm * 128 + wm + (lane >> 2);
        #pragma unroll
        for (int i = 0; i < 4; i++) {
            atomicAdd(&g_diffpre[mbase + i * 16], part0[i]);
            atomicAdd(&g_diffpre[mbase + i * 16 + 8], part1[i]);
        }
    }
}

// ---------------- finalize: 4 tokens/warp, fused importance ----------------
__global__ __launch_bounds__(256)
void finalize_kernel(float* __restrict__ out) {
    __shared__ float simp[8 * 64];
    int warp = threadIdx.x >> 5;
    int lane = threadIdx.x & 31;
    int tbase = blockIdx.x * 32 + warp * 4;

    float2 lg[4]; float dp[4];
    #pragma unroll
    for (int tt = 0; tt < 4; tt++) {
        lg[tt] = *(const float2*)&g_logits[(size_t)(tbase + tt) * NEXP + lane * 2];
        dp[tt] = g_diffpre[tbase + tt];
    }

    float pimp0 = 0.f, pimp1 = 0.f;
    #pragma unroll
    for (int tt = 0; tt < 4; tt++) {
        int t = tbase + tt;
        float diff = 1.f / (1.f + expf(-dp[tt]));
        float denom = 1.f + diff;
        float l0 = lg[tt].x / denom;
        float l1 = lg[tt].y / denom;

        float e0 = expf(l0), e1 = expf(l1);
        float sum = e0 + e1;
        #pragma unroll
        for (int off = 16; off; off >>= 1) sum += __shfl_xor_sync(0xffffffffu, sum, off);
        float inv = 1.f / sum;
        float p0 = e0 * inv, p1 = e1 * inv;
        *(float2*)&out[OFF_P + (size_t)t * NEXP + lane * 2] = make_float2(p0, p1);
        pimp0 += p0; pimp1 += p1;

        float bv; int bi;
        if (l1 > l0) { bv = l1; bi = lane * 2 + 1; } else { bv = l0; bi = lane * 2; }
        #pragma unroll
        for (int off = 16; off; off >>= 1) {
            float ov = __shfl_xor_sync(0xffffffffu, bv, off);
            int   oi = __shfl_xor_sync(0xffffffffu, bi, off);
            if (ov > bv || (ov == bv && oi < bi)) { bv = ov; bi = oi; }
        }
        int top1 = bi;
        float c0 = (lane * 2     == top1) ? -INFINITY : l0;
        float c1 = (lane * 2 + 1 == top1) ? -INFINITY : l1;
        float bv2; int bi2;
        if (c1 > c0) { bv2 = c1; bi2 = lane * 2 + 1; } else { bv2 = c0; bi2 = lane * 2; }
        #pragma unroll
        for (int off = 16; off; off >>= 1) {
            float ov = __shfl_xor_sync(0xffffffffu, bv2, off);
            int   oi = __shfl_xor_sync(0xffffffffu, bi2, off);
            if (ov > bv2 || (ov == bv2 && oi < bi2)) { bv2 = ov; bi2 = oi; }
        }
        int top2 = bi2;

        float sel1 = (top1 & 1) ? p1 : p0;
        float pt1 = __shfl_sync(0xffffffffu, sel1, top1 >> 1);
        float sel2 = (top2 & 1) ? p1 : p0;
        float pt2 = __shfl_sync(0xffffffffu, sel2, top2 >> 1);

        float s1 = (1.0f - pt1) + pt1;
        float s2 = (1.0f - pt2) + pt2;
        float dsum = fmaxf(s1 + s2, 1e-9f);

        if (lane == 0) {
            out[OFF_IDX + t * 2]     = (float)top1;
            out[OFF_IDX + t * 2 + 1] = (float)top2;
            out[OFF_SC + t * 2]      = s1 / dsum;
            out[OFF_SC + t * 2 + 1]  = s2 / dsum;
            atomicAdd(&g_loadcnt[top1], 1);
            atomicAdd(&g_loadcnt[top2], 1);
        }
    }

    simp[warp * 64 + lane * 2]     = pimp0;
    simp[warp * 64 + lane * 2 + 1] = pimp1;
    __syncthreads();
    if (threadIdx.x < 64) {
        float a = 0.f;
        #pragma unroll
        for (int w = 0; w < 8; w++) a += simp[w * 64 + threadIdx.x];
        atomicAdd(&g_imp[threadIdx.x], a);
    }
}

// ---------------- write importance / load ----------------
__global__ void stats_out_kernel(float* __restrict__ out) {
    int e = threadIdx.x;
    out[OFF_IMP + e]  = g_imp[e] * (1.f / TOKENS);
    out[OFF_LOAD + e] = (float)g_loadcnt[e] * (1.f / TOKENS);
}

// ---------------- launch ----------------
extern "C" void kernel_launch(void* const* d_in, const int* in_sizes, int n_in,
                              void* d_out, int out_size) {
    const float* x     = (const float*)d_in[0];
    const float* Wg    = (const float*)d_in[1];
    const float* gamma = (const float*)d_in[2];
    const float* beta  = (const float*)d_in[3];
    const float* W1    = (const float*)d_in[4];
    const float* W2    = (const float*)d_in[5];
    float* out = (float*)d_out;

    cudaFuncSetAttribute(gemm1_mma, cudaFuncAttributeMaxDynamicSharedMemorySize, G2_SMEM);

    prep_kernel<<<(HDIM * DDIM) / 256, 256>>>(W1, Wg);
    ln_logits<<<TOKENS / 128, 512>>>(x);
    dim3 g3(HDIM / G2_BN, TOKENS / 128);
    gemm1_mma<<<g3, 256, G2_SMEM>>>(x, gamma, beta, W2);
    finalize_kernel<<<TOKENS / 32, 256>>>(out);
    stats_out_kernel<<<1, NEXP>>>(out);
}

// round 10
// speedup vs baseline: 1.1413x; 1.1413x over previous
#include <cuda_runtime.h>
#include <cuda_bf16.h>
#include <math.h>
#include <stdint.h>

#define TOKENS 16384
#define DDIM   2048
#define NEXP   64
#define HDIM   1024

// Output layout (float32): idx [16384*2] | scores [16384*2] | probs [16384*64] | imp [64] | load [64]
#define OFF_IDX   0
#define OFF_SC    32768
#define OFF_P     65536
#define OFF_IMP   1114112
#define OFF_LOAD  1114176

// ---------------- scratch ----------------
__device__ __nv_bfloat16 g_w1[(size_t)HDIM * DDIM];
__device__ __nv_bfloat16 g_wg_hi[(size_t)NEXP * DDIM];
__device__ __nv_bfloat16 g_wg_lo[(size_t)NEXP * DDIM];
__device__ float g_logits[(size_t)TOKENS * NEXP];
__device__ float g_diffpre[TOKENS];
__device__ float g_mu[TOKENS];
__device__ float g_rstd[TOKENS];
__device__ float g_imp[NEXP];
__device__ int   g_loadcnt[NEXP];

// ---------------- prep ----------------
__global__ void prep_kernel(const float* __restrict__ W1, const float* __restrict__ Wg) {
    int i = blockIdx.x * blockDim.x + threadIdx.x;
    g_w1[i] = __float2bfloat16(W1[i]);
    if (i < NEXP * DDIM) {
        float v = Wg[i];
        __nv_bfloat16 hi = __float2bfloat16(v);
        g_wg_hi[i] = hi;
        g_wg_lo[i] = __float2bfloat16(v - __bfloat162float(hi));
    }
    if (i < TOKENS) g_diffpre[i] = 0.f;
    if (i < NEXP) { g_loadcnt[i] = 0; g_imp[i] = 0.f; }
}

// =========================================================================
// ln_logits: LN stats + base-logits GEMM (bf16x3 split), double-buffered.
// One CTA = 128 tokens, 512 threads (16 warps, warp tile 16 x 32).
// Dynamic smem: 2 stages x (Ah|Al|Wh|Wl) + stats. ONE sync per chunk.
// =========================================================================
#define AST 40
#define LN_STG 15360   // bf16 elems per stage: Ah 5120 | Al 5120 | Wh 2560 | Wl 2560
#define LN_SMEM (2 * LN_STG * 2 + 4096)

__global__ __launch_bounds__(512)
void ln_logits(const float* __restrict__ x) {
    extern __shared__ __align__(16) __nv_bfloat16 SM[];
    float* sS = (float*)(SM + 2 * LN_STG);
    float* sQ = sS + 512;

    int tile = blockIdx.x;
    int tid = threadIdx.x;
    int warp = tid >> 5, lane = tid & 31;
    const float* xb = x + (size_t)tile * 128 * DDIM;

    int lr = tid >> 2;          // 0..127 row
    int lc = (tid & 3) * 8;     // 0,8,16,24
    int wr = tid >> 2;          // 0..63 for W (tid<256)
    int wm = (warp & 7) * 16;
    int wn2 = (warp >> 3) * 32;

    float s = 0.f, q = 0.f;
    float acc[4][4];
    #pragma unroll
    for (int j = 0; j < 4; j++)
        #pragma unroll
        for (int r = 0; r < 4; r++) acc[j][r] = 0.f;

    float4 v0 = *(const float4*)&xb[(size_t)lr * DDIM + lc];
    float4 v1 = *(const float4*)&xb[(size_t)lr * DDIM + lc + 4];
    uint4 wh, wl;
    if (tid < 256) {
        wh = *(const uint4*)&g_wg_hi[(size_t)wr * DDIM + lc];
        wl = *(const uint4*)&g_wg_lo[(size_t)wr * DDIM + lc];
    }

    // convert chunk 0 into stage 0 (+ stats)
    {
        __nv_bfloat16* Ah = SM;
        __nv_bfloat16* Al = SM + 5120;
        s += v0.x + v0.y + v0.z + v0.w + v1.x + v1.y + v1.z + v1.w;
        q += v0.x*v0.x + v0.y*v0.y + v0.z*v0.z + v0.w*v0.w
           + v1.x*v1.x + v1.y*v1.y + v1.z*v1.z + v1.w*v1.w;
        __align__(16) __nv_bfloat16 hb[8], lb[8];
        float vv[8] = {v0.x, v0.y, v0.z, v0.w, v1.x, v1.y, v1.z, v1.w};
        #pragma unroll
        for (int i = 0; i < 8; i++) {
            __nv_bfloat16 b = __float2bfloat16(vv[i]);
            hb[i] = b;
            lb[i] = __float2bfloat16(vv[i] - __bfloat162float(b));
        }
        *(uint4*)&Ah[lr * AST + lc] = *(uint4*)hb;
        *(uint4*)&Al[lr * AST + lc] = *(uint4*)lb;
        if (tid < 256) {
            *(uint4*)&SM[10240 + wr * AST + lc] = wh;
            *(uint4*)&SM[12800 + wr * AST + lc] = wl;
        }
    }
    __syncthreads();

    #pragma unroll 2
    for (int kc = 0; kc < 64; kc++) {
        // issue global loads for chunk kc+1 (latency hidden by MMA below)
        if (kc < 63) {
            int k0n = (kc + 1) * 32;
            v0 = *(const float4*)&xb[(size_t)lr * DDIM + k0n + lc];
            v1 = *(const float4*)&xb[(size_t)lr * DDIM + k0n + lc + 4];
            if (tid < 256) {
                wh = *(const uint4*)&g_wg_hi[(size_t)wr * DDIM + k0n + lc];
                wl = *(const uint4*)&g_wg_lo[(size_t)wr * DDIM + k0n + lc];
            }
        }

        // MMA from stage kc&1
        {
            const __nv_bfloat16* Ahs = SM + (kc & 1) * LN_STG;
            const __nv_bfloat16* Als = Ahs + 5120;
            const __nv_bfloat16* Whs = Ahs + 10240;
            const __nv_bfloat16* Wls = Ahs + 12800;
            #pragma unroll
            for (int ks = 0; ks < 2; ks++) {
                int arow = wm + (lane >> 2);
                int colb = (lane & 3) * 2 + ks * 16;
                const __nv_bfloat16* pa  = &Ahs[arow * AST + colb];
                const __nv_bfloat16* pal = &Als[arow * AST + colb];
                uint32_t ah[4], al[4];
                ah[0] = *(const uint32_t*)(pa);
                ah[1] = *(const uint32_t*)(pa + 8 * AST);
                ah[2] = *(const uint32_t*)(pa + 8);
                ah[3] = *(const uint32_t*)(pa + 8 * AST + 8);
                al[0] = *(const uint32_t*)(pal);
                al[1] = *(const uint32_t*)(pal + 8 * AST);
                al[2] = *(const uint32_t*)(pal + 8);
                al[3] = *(const uint32_t*)(pal + 8 * AST + 8);
                #pragma unroll
                for (int j = 0; j < 4; j++) {
                    int brow = wn2 + j * 8 + (lane >> 2);
                    const __nv_bfloat16* pb  = &Whs[brow * AST + colb];
                    const __nv_bfloat16* pbl = &Wls[brow * AST + colb];
                    uint32_t bh0 = *(const uint32_t*)(pb);
                    uint32_t bh1 = *(const uint32_t*)(pb + 8);
                    uint32_t bl0 = *(const uint32_t*)(pbl);
                    uint32_t bl1 = *(const uint32_t*)(pbl + 8);
                    asm volatile(
                        "mma.sync.aligned.m16n8k16.row.col.f32.bf16.bf16.f32 "
                        "{%0,%1,%2,%3}, {%4,%5,%6,%7}, {%8,%9}, {%0,%1,%2,%3};\n"
                        : "+f"(acc[j][0]), "+f"(acc[j][1]), "+f"(acc[j][2]), "+f"(acc[j][3])
                        : "r"(ah[0]), "r"(ah[1]), "r"(ah[2]), "r"(ah[3]), "r"(bh0), "r"(bh1));
                    asm volatile(
                        "mma.sync.aligned.m16n8k16.row.col.f32.bf16.bf16.f32 "
                        "{%0,%1,%2,%3}, {%4,%5,%6,%7}, {%8,%9}, {%0,%1,%2,%3};\n"
                        : "+f"(acc[j][0]), "+f"(acc[j][1]), "+f"(acc[j][2]), "+f"(acc[j][3])
                        : "r"(ah[0]), "r"(ah[1]), "r"(ah[2]), "r"(ah[3]), "r"(bl0), "r"(bl1));
                    asm volatile(
                        "mma.sync.aligned.m16n8k16.row.col.f32.bf16.bf16.f32 "
                        "{%0,%1,%2,%3}, {%4,%5,%6,%7}, {%8,%9}, {%0,%1,%2,%3};\n"
                        : "+f"(acc[j][0]), "+f"(acc[j][1]), "+f"(acc[j][2]), "+f"(acc[j][3])
                        : "r"(al[0]), "r"(al[1]), "r"(al[2]), "r"(al[3]), "r"(bh0), "r"(bh1));
                }
            }
        }

        // convert chunk kc+1 into stage (kc+1)&1 (+ stats)
        if (kc < 63) {
            __nv_bfloat16* Ahn = SM + ((kc + 1) & 1) * LN_STG;
            __nv_bfloat16* Aln = Ahn + 5120;
            s += v0.x + v0.y + v0.z + v0.w + v1.x + v1.y + v1.z + v1.w;
            q += v0.x*v0.x + v0.y*v0.y + v0.z*v0.z + v0.w*v0.w
               + v1.x*v1.x + v1.y*v1.y + v1.z*v1.z + v1.w*v1.w;
            __align__(16) __nv_bfloat16 hb[8], lb[8];
            float vv[8] = {v0.x, v0.y, v0.z, v0.w, v1.x, v1.y, v1.z, v1.w};
            #pragma unroll
            for (int i = 0; i < 8; i++) {
                __nv_bfloat16 b = __float2bfloat16(vv[i]);
                hb[i] = b;
                lb[i] = __float2bfloat16(vv[i] - __bfloat162float(b));
            }
            *(uint4*)&Ahn[lr * AST + lc] = *(uint4*)hb;
            *(uint4*)&Aln[lr * AST + lc] = *(uint4*)lb;
            if (tid < 256) {
                *(uint4*)&Ahn[10240 + wr * AST + lc] = wh;
                *(uint4*)&Ahn[12800 + wr * AST + lc] = wl;
            }
        }
        __syncthreads();
    }

    sS[lr * 4 + (tid & 3)] = s;
    sQ[lr * 4 + (tid & 3)] = q;
    __syncthreads();
    if (tid < 128) {
        float ts = sS[tid*4] + sS[tid*4+1] + sS[tid*4+2] + sS[tid*4+3];
        float tq = sQ[tid*4] + sQ[tid*4+1] + sQ[tid*4+2] + sQ[tid*4+3];
        float mean = ts * (1.f / DDIM);
        float var  = tq * (1.f / DDIM) - mean * mean;
        g_mu[tile * 128 + tid]   = mean;
        g_rstd[tile * 128 + tid] = rsqrtf(var + 1e-5f);
    }

    #pragma unroll
    for (int j = 0; j < 4; j++) {
        int row = tile * 128 + wm + (lane >> 2);
        int col = wn2 + j * 8 + (lane & 3) * 2;
        float2 c01; c01.x = acc[j][0]; c01.y = acc[j][1];
        float2 c23; c23.x = acc[j][2]; c23.y = acc[j][3];
        *(float2*)&g_logits[(size_t)row * NEXP + col] = c01;
        *(float2*)&g_logits[(size_t)(row + 8) * NEXP + col] = c23;
    }
}

// =========================================================================
// gemm1 (R7-proven): BM=128 x BN=256 x BK=32, bf16 MMA fp32 accum,
// LN applied in-kernel from x fp32, 3-stage cp.async B-ring.
// =========================================================================
#define G2_STAGES 3
#define G2_BK     32
#define G2_BN     256
#define G2_BBYTES 16384
#define G2_ABYTES 8192
#define G2_A_OFF  (G2_STAGES * G2_BBYTES)
#define G2_GB_OFF (G2_A_OFF + 2 * G2_ABYTES)
#define G2_SMEM   (G2_GB_OFF + 16384)
#define G2_CHUNKS (DDIM / G2_BK)

__device__ __forceinline__ uint32_t smem_u32(const void* p) {
    uint32_t a;
    asm("{ .reg .u64 t; cvta.to.shared.u64 t, %1; cvt.u32.u64 %0, t; }" : "=r"(a) : "l"(p));
    return a;
}
__device__ __forceinline__ uint32_t g1_sw(uint32_t r, uint32_t c) {
    return r * 64 + ((c ^ ((r >> 1) & 3)) * 16);
}
__device__ __forceinline__ void ldsm_x4(uint32_t& r0, uint32_t& r1, uint32_t& r2, uint32_t& r3,
                                        uint32_t addr) {
    asm volatile("ldmatrix.sync.aligned.m8n8.x4.shared.b16 {%0,%1,%2,%3}, [%4];"
                 : "=r"(r0), "=r"(r1), "=r"(r2), "=r"(r3) : "r"(addr));
}
__device__ __forceinline__ float gelu_exact(float v) {
    return 0.5f * v * (1.0f + erff(v * 0.70710678118654752440f));
}

__device__ __forceinline__ void g2_stage_B(uint32_t sB, const __nv_bfloat16* Bg,
                                           int k0, int tid) {
    #pragma unroll
    for (int i = 0; i < 4; i++) {
        int idx = tid + i * 256;
        int r = idx >> 2, c = idx & 3;
        uint32_t dst = sB + g1_sw(r, c);
        asm volatile("cp.async.cg.shared.global [%0], [%1], 16;\n"
                     :: "r"(dst), "l"(Bg + (size_t)r * DDIM + k0 + c * 8));
    }
    asm volatile("cp.async.commit_group;\n");
}

__global__ __launch_bounds__(256, 1)
void gemm1_mma(const float* __restrict__ x, const float* __restrict__ gamma,
               const float* __restrict__ beta, const float* __restrict__ W2) {
    extern __shared__ __align__(128) char g1sm[];
    uint32_t sb = smem_u32(g1sm);
    int tid = threadIdx.x;
    int warp = tid >> 5, lane = tid & 31;
    int bn = blockIdx.x, bm = blockIdx.y;
    int wm = (warp & 1) * 64;
    int wn = (warp >> 1) * 64;

    const float* xb = x + (size_t)(bm * 128) * DDIM;
    const __nv_bfloat16* Bg = g_w1 + (size_t)(bn * G2_BN) * DDIM;

    float* sGB = (float*)(g1sm + G2_GB_OFF);
    #pragma unroll
    for (int i = 0; i < 2; i++) {
        int idx = tid + i * 256;
        ((float4*)sGB)[idx]       = ((const float4*)gamma)[idx];
        ((float4*)sGB)[idx + 512] = ((const float4*)beta)[idx];
    }

    int r0 = tid >> 1;
    int hsel = tid & 1;
    float mu = g_mu[bm * 128 + r0];
    float rs = g_rstd[bm * 128 + r0];

    float acc[4][8][4];
    #pragma unroll
    for (int i = 0; i < 4; i++)
        #pragma unroll
        for (int j = 0; j < 8; j++)
            #pragma unroll
            for (int r = 0; r < 4; r++) acc[i][j][r] = 0.f;

    g2_stage_B(sb + 0 * G2_BBYTES, Bg, 0, tid);
    g2_stage_B(sb + 1 * G2_BBYTES, Bg, G2_BK, tid);
    float4 xv[4];
    #pragma unroll
    for (int i = 0; i < 4; i++)
        xv[i] = *(const float4*)&xb[(size_t)r0 * DDIM + hsel * 16 + i * 4];

    __syncthreads();

    int lrow = lane & 15;
    int lsel = lane >> 4;

    #pragma unroll 1
    for (int c = 0; c < G2_CHUNKS; c++) {
        if (c + 2 < G2_CHUNKS)
            g2_stage_B(sb + ((c + 2) % G2_STAGES) * G2_BBYTES, Bg, (c + 2) * G2_BK, tid);

        {
            const float* gg = sGB + c * 32 + hsel * 16;
            const float* bb = gg + 2048;
            uint32_t sA = sb + G2_A_OFF + (c & 1) * G2_ABYTES;
            __align__(16) __nv_bfloat16 ob[16];
            #pragma unroll
            for (int i = 0; i < 4; i++) {
                float4 t4 = xv[i];
                float4 g4 = *(const float4*)(gg + i * 4);
                float4 b4 = *(const float4*)(bb + i * 4);
                ob[i*4+0] = __float2bfloat16((t4.x - mu) * rs * g4.x + b4.x);
                ob[i*4+1] = __float2bfloat16((t4.y - mu) * rs * g4.y + b4.y);
                ob[i*4+2] = __float2bfloat16((t4.z - mu) * rs * g4.z + b4.z);
                ob[i*4+3] = __float2bfloat16((t4.w - mu) * rs * g4.w + b4.w);
            }
            #pragma unroll
            for (int j = 0; j < 2; j++) {
                uint32_t dst = sA + g1_sw((uint32_t)r0, (uint32_t)(hsel * 2 + j));
                *(uint4*)(g1sm + (dst - sb)) = *(uint4*)&ob[j * 8];
            }
        }

        if (c + 1 < G2_CHUNKS) {
            #pragma unroll
            for (int i = 0; i < 4; i++)
                xv[i] = *(const float4*)&xb[(size_t)r0 * DDIM + (c + 1) * G2_BK + hsel * 16 + i * 4];
        }

        if (c + 2 < G2_CHUNKS) {
            asm volatile("cp.async.wait_group 2;\n");
        } else if (c + 2 == G2_CHUNKS) {
            asm volatile("cp.async.wait_group 1;\n");
        } else {
            asm volatile("cp.async.wait_group 0;\n");
        }
        __syncthreads();

        uint32_t sA = sb + G2_A_OFF + (c & 1) * G2_ABYTES;
        uint32_t sB = sb + (c % G2_STAGES) * G2_BBYTES;

        #pragma unroll
        for (int ks = 0; ks < 2; ks++) {
            uint32_t af[4][4], bf[8][2];
            #pragma unroll
            for (int i = 0; i < 4; i++) {
                uint32_t r = (uint32_t)(wm + i * 16 + lrow);
                ldsm_x4(af[i][0], af[i][1], af[i][2], af[i][3],
                        sA + g1_sw(r, (uint32_t)(ks * 2 + lsel)));
            }
            #pragma unroll
            for (int jb = 0; jb < 4; jb++) {
                uint32_t r = (uint32_t)(wn + jb * 16 + lrow);
                uint32_t q0, q1, q2, q3;
                ldsm_x4(q0, q1, q2, q3, sB + g1_sw(r, (uint32_t)(ks * 2 + lsel)));
                bf[jb * 2][0] = q0;     bf[jb * 2][1] = q2;
                bf[jb * 2 + 1][0] = q1; bf[jb * 2 + 1][1] = q3;
            }
            #pragma unroll
            for (int i = 0; i < 4; i++)
                #pragma unroll
                for (int j = 0; j < 8; j++) {
                    asm volatile(
                        "mma.sync.aligned.m16n8k16.row.col.f32.bf16.bf16.f32 "
                        "{%0,%1,%2,%3}, {%4,%5,%6,%7}, {%8,%9}, {%0,%1,%2,%3};\n"
                        : "+f"(acc[i][j][0]), "+f"(acc[i][j][1]),
                          "+f"(acc[i][j][2]), "+f"(acc[i][j][3])
                        : "r"(af[i][0]), "r"(af[i][1]), "r"(af[i][2]), "r"(af[i][3]),
                          "r"(bf[j][0]), "r"(bf[j][1]));
                }
        }
        __syncthreads();
    }

    float part0[4] = {0.f, 0.f, 0.f, 0.f};
    float part1[4] = {0.f, 0.f, 0.f, 0.f};
    #pragma unroll
    for (int j = 0; j < 8; j++) {
        int n = bn * G2_BN + wn + j * 8 + (lane & 3) * 2;
        float w20 = W2[n], w21 = W2[n + 1];
        #pragma unroll
        for (int i = 0; i < 4; i++) {
            part0[i] += gelu_exact(acc[i][j][0]) * w20 + gelu_exact(acc[i][j][1]) * w21;
            part1[i] += gelu_exact(acc[i][j][2]) * w20 + gelu_exact(acc[i][j][3]) * w21;
        }
    }
    #pragma unroll
    for (int i = 0; i < 4; i++) {
        part0[i] += __shfl_xor_sync(0xffffffffu, part0[i], 1);
        part0[i] += __shfl_xor_sync(0xffffffffu, part0[i], 2);
        part1[i] += __shfl_xor_sync(0xffffffffu, part1[i], 1);
        part1[i] += __shfl_xor_sync(0xffffffffu, part1[i], 2);
    }
    if ((lane & 3) == 0) {
        int mbase = bm * 128 + wm + (lane >> 2);
        #pragma unroll
        for (int i = 0; i < 4; i++) {
            atomicAdd(&g_diffpre[mbase + i * 16], part0[i]);
            atomicAdd(&g_diffpre[mbase + i * 16 + 8], part1[i]);
        }
    }
}

// ---------------- finalize: 4 tokens/warp, fast exp, recip denom ----------------
__global__ __launch_bounds__(256)
void finalize_kernel(float* __restrict__ out) {
    __shared__ float simp[8 * 64];
    int warp = threadIdx.x >> 5;
    int lane = threadIdx.x & 31;
    int tbase = blockIdx.x * 32 + warp * 4;

    float2 lg[4]; float dp[4];
    #pragma unroll
    for (int tt = 0; tt < 4; tt++) {
        lg[tt] = *(const float2*)&g_logits[(size_t)(tbase + tt) * NEXP + lane * 2];
        dp[tt] = g_diffpre[tbase + tt];
    }

    float pimp0 = 0.f, pimp1 = 0.f;
    #pragma unroll
    for (int tt = 0; tt < 4; tt++) {
        int t = tbase + tt;
        float diff = 1.f / (1.f + __expf(-dp[tt]));
        float rden = 1.f / (1.f + diff);
        float l0 = lg[tt].x * rden;
        float l1 = lg[tt].y * rden;

        float e0 = __expf(l0), e1 = __expf(l1);
        float sum = e0 + e1;
        #pragma unroll
        for (int off = 16; off; off >>= 1) sum += __shfl_xor_sync(0xffffffffu, sum, off);
        float inv = 1.f / sum;
        float p0 = e0 * inv, p1 = e1 * inv;
        *(float2*)&out[OFF_P + (size_t)t * NEXP + lane * 2] = make_float2(p0, p1);
        pimp0 += p0; pimp1 += p1;

        float bv; int bi;
        if (l1 > l0) { bv = l1; bi = lane * 2 + 1; } else { bv = l0; bi = lane * 2; }
        #pragma unroll
        for (int off = 16; off; off >>= 1) {
            float ov = __shfl_xor_sync(0xffffffffu, bv, off);
            int   oi = __shfl_xor_sync(0xffffffffu, bi, off);
            if (ov > bv || (ov == bv && oi < bi)) { bv = ov; bi = oi; }
        }
        int top1 = bi;
        float c0 = (lane * 2     == top1) ? -INFINITY : l0;
        float c1 = (lane * 2 + 1 == top1) ? -INFINITY : l1;
        float bv2; int bi2;
        if (c1 > c0) { bv2 = c1; bi2 = lane * 2 + 1; } else { bv2 = c0; bi2 = lane * 2; }
        #pragma unroll
        for (int off = 16; off; off >>= 1) {
            float ov = __shfl_xor_sync(0xffffffffu, bv2, off);
            int   oi = __shfl_xor_sync(0xffffffffu, bi2, off);
            if (ov > bv2 || (ov == bv2 && oi < bi2)) { bv2 = ov; bi2 = oi; }
        }
        int top2 = bi2;

        float sel1 = (top1 & 1) ? p1 : p0;
        float pt1 = __shfl_sync(0xffffffffu, sel1, top1 >> 1);
        float sel2 = (top2 & 1) ? p1 : p0;
        float pt2 = __shfl_sync(0xffffffffu, sel2, top2 >> 1);

        float s1 = (1.0f - pt1) + pt1;
        float s2 = (1.0f - pt2) + pt2;
        float dsum = fmaxf(s1 + s2, 1e-9f);

        if (lane == 0) {
            out[OFF_IDX + t * 2]     = (float)top1;
            out[OFF_IDX + t * 2 + 1] = (float)top2;
            out[OFF_SC + t * 2]      = s1 / dsum;
            out[OFF_SC + t * 2 + 1]  = s2 / dsum;
            atomicAdd(&g_loadcnt[top1], 1);
            atomicAdd(&g_loadcnt[top2], 1);
        }
    }

    simp[warp * 64 + lane * 2]     = pimp0;
    simp[warp * 64 + lane * 2 + 1] = pimp1;
    __syncthreads();
    if (threadIdx.x < 64) {
        float a = 0.f;
        #pragma unroll
        for (int w = 0; w < 8; w++) a += simp[w * 64 + threadIdx.x];
        atomicAdd(&g_imp[threadIdx.x], a);
    }
}

// ---------------- write importance / load ----------------
__global__ void stats_out_kernel(float* __restrict__ out) {
    int e = threadIdx.x;
    out[OFF_IMP + e]  = g_imp[e] * (1.f / TOKENS);
    out[OFF_LOAD + e] = (float)g_loadcnt[e] * (1.f / TOKENS);
}

// ---------------- launch ----------------
extern "C" void kernel_launch(void* const* d_in, const int* in_sizes, int n_in,
                              void* d_out, int out_size) {
    const float* x     = (const float*)d_in[0];
    const float* Wg    = (const float*)d_in[1];
    const float* gamma = (const float*)d_in[2];
    const float* beta  = (const float*)d_in[3];
    const float* W1    = (const float*)d_in[4];
    const float* W2    = (const float*)d_in[5];
    float* out = (float*)d_out;

    cudaFuncSetAttribute(gemm1_mma, cudaFuncAttributeMaxDynamicSharedMemorySize, G2_SMEM);
    cudaFuncSetAttribute(ln_logits, cudaFuncAttributeMaxDynamicSharedMemorySize, LN_SMEM);

    prep_kernel<<<(HDIM * DDIM) / 256, 256>>>(W1, Wg);
    ln_logits<<<TOKENS / 128, 512, LN_SMEM>>>(x);
    dim3 g3(HDIM / G2_BN, TOKENS / 128);
    gemm1_mma<<<g3, 256, G2_SMEM>>>(x, gamma, beta, W2);
    finalize_kernel<<<TOKENS / 32, 256>>>(out);
    stats_out_kernel<<<1, NEXP>>>(out);
}